// round 8
// baseline (speedup 1.0000x reference)
#include <cuda_runtime.h>

#define N_NODES 20000
#define N_EDGES 50000
#define H 64
#define HH 4096
#define NREG 65
#define GE 16
#define WARPS 4
#define SUBIT 4
#define BLK_SLOTS (WARPS * SUBIT * GE)    // 256 slots per block
#define EPAD (N_EDGES + NREG * GE)
#define NPB 32
#define RBLOCKS (N_NODES / NPB)           // 625 k_root blocks

typedef unsigned long long u64;

// ---------------- scratch ----------------
// d_Qbuf layout per region r (float base = r*2*HH):
//   Q0 pair-permuted: float idx (i>>1)*128 + 2*o + (i&1)   [so {Q[2c][o],Q[2c+1][o]} is one aligned 8B pair]
//   Q1 same at +HH
__device__ __align__(16) float d_Qbuf[NREG * 2 * HH];
__device__ __align__(16) float d_Bs[H];
__device__ __align__(16) int   d_Bidx[H];    // neuron index per rank
__device__ __align__(16) int   d_Brank[H];   // rank per neuron
__device__ __align__(16) int   d_regid[N_EDGES];
__device__ __align__(16) int   d_hist[NREG];
__device__ __align__(16) int   d_cursor[NREG];
__device__ __align__(16) int   d_sorted[EPAD];
__device__ __align__(16) float d_part[RBLOCKS * 2 * H];
__device__ __align__(16) float d_sums[2 * H];

// packed f32x2 fma: d = a*b + d (elementwise on pairs)
__device__ __forceinline__ void fma2(u64& d, u64 a, u64 b) {
    asm("fma.rn.f32x2 %0, %1, %2, %0;" : "+l"(d) : "l"(a), "l"(b));
}
__device__ __forceinline__ float hadd2(u64 v) {
    unsigned lo, hi;
    asm("mov.b64 {%0, %1}, %2;" : "=r"(lo), "=r"(hi) : "l"(v));
    return __uint_as_float(lo) + __uint_as_float(hi);
}

// ---------------- 0a) zero output ----------------
__global__ void k_zero_out(float* out) {
    int i = blockIdx.x * blockDim.x + threadIdx.x;
    if (i < N_NODES * H) out[i] = 0.0f;
}

// ---------------- 0b) small inits ----------------
__global__ void k_init() {
    int i = blockIdx.x * blockDim.x + threadIdx.x;
    if (i < NREG) { d_hist[i] = 0; d_cursor[i] = 0; }
    if (i < EPAD) d_sorted[i] = -1;
}

// ---------------- 1) breakpoints + rank sort (1 block, 64 thr) -------------
__global__ void k_prep(const float* w1, const float* b1) {
    __shared__ float t[H];
    int k = threadIdx.x;
    float w = w1[k];
    float tb = (w == 0.0f) ? 1e30f : (-b1[k] / w);
    t[k] = tb;
    __syncthreads();
    int rank = 0;
    for (int j = 0; j < H; j++) {
        float tj = t[j];
        rank += (tj < tb) || (tj == tb && j < k);
    }
    d_Bs[rank] = tb;
    d_Bidx[rank] = k;
    d_Brank[k] = rank;
}

// ---------------- 2) Q0/Q1: 4 checkpoint chunks x rank-1 updates -----------
// grid = 128 blocks: (blockIdx & 31) = m-group, (blockIdx >> 5) = chunk
__global__ void __launch_bounds__(128) k_q(const float* w1, const float* b1,
                                           const float* b2, const float* w2) {
    __shared__ float w2sh[128][H + 1];
    __shared__ float mb[H], mw[H], dB[H], dW[H];
    __shared__ int   cix[H];

    int t = threadIdx.x;
    int mg = blockIdx.x & 31, chunk = blockIdx.x >> 5;
    int r0 = chunk * 17;
    int rend = (r0 + 17 < NREG) ? r0 + 17 : NREG;
    int mbase = mg * 128;

    for (int i2 = t; i2 < 128 * H; i2 += 128) {
        int ml = i2 >> 6, k = i2 & 63;
        w2sh[ml][k] = w2[(mbase + ml) * H + k];
    }
    if (t < H) {
        int k = t;
        float w = w1[k], b = b1[k];
        int rk = d_Brank[k];
        // active in region r0: w>0 -> rank<r0 ; w<0 -> rank>=r0 ; w==0 -> b>0
        bool act = (w > 0.0f) ? (rk < r0) : ((w < 0.0f) ? (rk >= r0) : (b > 0.0f));
        mb[k] = act ? b : 0.0f;
        mw[k] = act ? w : 0.0f;
        int kr = d_Bidx[t];
        float wr = w1[kr], br = b1[kr];
        float sgn = (wr > 0.0f) ? 1.0f : -1.0f;
        dB[t] = sgn * br;
        dW[t] = sgn * wr;
        cix[t] = kr;
    }
    __syncthreads();

    int m = mbase + t;
    int i = m >> 6, o = m & 63;
    int p = (i >> 1) * 128 + 2 * o + (i & 1);   // pair-permuted index
    const float* row = w2sh[t];
    float q0 = b2[m];
    float q1 = 0.0f;
    #pragma unroll 8
    for (int k = 0; k < H; k++) {
        float v = row[k];
        q0 = fmaf(mb[k], v, q0);
        q1 = fmaf(mw[k], v, q1);
    }
    for (int r = r0; r < rend; r++) {
        d_Qbuf[r * (2 * HH) + p]      = q0;
        d_Qbuf[r * (2 * HH) + HH + p] = q1;
        if (r < H) {
            float v = row[cix[r]];
            q0 = fmaf(dB[r], v, q0);
            q1 = fmaf(dW[r], v, q1);
        }
    }
}

// ---------------- 3) region id per edge + histogram ----------------
__global__ void k_region(const float* ea) {
    __shared__ float Bs[H];
    __shared__ int bh[NREG];
    int t = threadIdx.x;
    if (t < H) Bs[t] = d_Bs[t];
    if (t < NREG) bh[t] = 0;
    __syncthreads();
    int e = blockIdx.x * blockDim.x + t;
    if (e < N_EDGES) {
        float a = ea[e];
        int r = 0;
        #pragma unroll 8
        for (int k = 0; k < H; k++) r += (Bs[k] <= a) ? 1 : 0;
        d_regid[e] = r;
        atomicAdd(&bh[r], 1);
    }
    __syncthreads();
    if (t < NREG && bh[t] > 0) atomicAdd(&d_hist[t], bh[t]);
}

// ---------------- 4) GE-aligned offsets ----------------
__global__ void k_offsets() {
    if (threadIdx.x == 0) {
        int s = 0;
        for (int r = 0; r < NREG; r++) {
            d_cursor[r] = s;
            s += (d_hist[r] + (GE - 1)) & ~(GE - 1);
        }
    }
}

// ---------------- 5) scatter edges into region-sorted list ----------------
__global__ void k_scatter() {
    int e = blockIdx.x * blockDim.x + threadIdx.x;
    if (e < N_EDGES) {
        int r = d_regid[e];
        int pos = atomicAdd(&d_cursor[r], 1);
        d_sorted[pos] = e;
    }
}

// ---------------- 6) message + scatter-add (hot kernel, f32x2) -------------
// Warp-local: each warp processes SUBIT batches of GE edges; for each batch,
// pairs the contraction dim into f32x2 FMAs and flushes via red.v2 atomics.
__global__ void __launch_bounds__(128) k_msg(const float* x, const float* ea,
                                             const int* ei, float* out) {
    __shared__ u64   xsp[WARPS][GE][32];   // {x[2c], x[2c+1]} per edge
    __shared__ float sa[WARPS][GE];
    __shared__ int   ssrc[WARPS][GE];
    __shared__ int   sdst[WARPS][GE];
    __shared__ int   sreg[WARPS][GE];

    int w = threadIdx.x >> 5;
    int lane = threadIdx.x & 31;
    int gw = blockIdx.x * WARPS + w;

    for (int it = 0; it < SUBIT; it++) {
        int base = (gw * SUBIT + it) * GE;
        if (lane < GE) {
            int slot = base + lane;
            int eid = (slot < EPAD) ? d_sorted[slot] : -1;
            int src = -1, dst = 0, r = -1;
            float a = 0.0f;
            if (eid >= 0) {
                a = ea[eid];
                src = ei[eid];
                dst = ei[N_EDGES + eid];
                r = d_regid[eid];
                if (src < 0 || src >= N_NODES || dst < 0 || dst >= N_NODES) {
                    src = -1; dst = 0;
                }
            }
            sa[w][lane] = a; ssrc[w][lane] = src;
            sdst[w][lane] = dst; sreg[w][lane] = r;
        }
        __syncwarp();
        int rr = -1;
        #pragma unroll
        for (int j = 0; j < GE; j++) { int rg = sreg[w][j]; rr = (rg > rr) ? rg : rr; }
        if (rr < 0) continue;   // warp-uniform

        #pragma unroll
        for (int j = 0; j < GE; j++) {
            int s = ssrc[w][j];
            u64 v = 0ULL;
            if (s >= 0) v = *reinterpret_cast<const u64*>(x + s * H + 2 * lane);
            xsp[w][j][lane] = v;
        }
        __syncwarp();

        const float* Qr = d_Qbuf + rr * (2 * HH);
        #pragma unroll
        for (int pass = 0; pass < 2; pass++) {
            int o = pass * 32 + lane;
            u64 acc0[GE], acc1[GE];
            #pragma unroll
            for (int j = 0; j < GE; j++) { acc0[j] = 0ULL; acc1[j] = 0ULL; }
            #pragma unroll 4
            for (int c = 0; c < 32; c++) {
                u64 q0 = *reinterpret_cast<const u64*>(Qr + c * 128 + 2 * o);
                u64 q1 = *reinterpret_cast<const u64*>(Qr + HH + c * 128 + 2 * o);
                #pragma unroll
                for (int j = 0; j < GE; j++) {
                    u64 xv = xsp[w][j][c];
                    fma2(acc0[j], xv, q0);
                    fma2(acc1[j], xv, q1);
                }
            }
            #pragma unroll
            for (int j = 0; j < GE; j++) {
                float v = 0.0f;
                bool live = (ssrc[w][j] >= 0);
                if (live) v = hadd2(acc0[j]) + sa[w][j] * hadd2(acc1[j]);
                float vh = __shfl_down_sync(0xFFFFFFFF, v, 1);
                if (live && (lane & 1) == 0) {
                    float* p = out + sdst[w][j] * H + o;   // o even
                    asm volatile("red.global.add.v2.f32 [%0], {%1, %2};"
                                 :: "l"(p), "f"(v), "f"(vh) : "memory");
                }
            }
        }
    }
}

// ---------------- 7) root GEMM + bias + agg(out); BN partials --------------
__global__ void k_root(const float* x, const float* rw,
                       const float* cb, float* out) {
    __shared__ float rws[HH];
    __shared__ float xrs[4][H];
    __shared__ float red[256];
    int t = threadIdx.x;
    for (int idx = t; idx < HH; idx += 256) {
        int oo = idx >> 6, ii = idx & 63;
        rws[ii * H + oo] = rw[idx];
    }
    int o = t & 63, nl = t >> 6;
    __syncthreads();
    float cbo = cb[o];
    float psum = 0.0f, psq = 0.0f;
    int n0 = blockIdx.x * NPB;
    for (int c = 0; c < NPB; c += 4) {
        int n = n0 + c + nl;
        xrs[nl][o] = x[n * H + o];
        __syncthreads();
        float acc = 0.0f;
        #pragma unroll 8
        for (int i = 0; i < H; i++) acc = fmaf(xrs[nl][i], rws[i * H + o], acc);
        float val = acc + out[n * H + o] + cbo;
        out[n * H + o] = val;
        psum += val;
        psq = fmaf(val, val, psq);
        __syncthreads();
    }
    red[t] = psum; __syncthreads();
    if (nl < 2) red[t] += red[t + 128];
    __syncthreads();
    if (nl == 0) d_part[blockIdx.x * (2 * H) + o] = red[t] + red[t + 64];
    __syncthreads();
    red[t] = psq; __syncthreads();
    if (nl < 2) red[t] += red[t + 128];
    __syncthreads();
    if (nl == 0) d_part[blockIdx.x * (2 * H) + H + o] = red[t] + red[t + 64];
}

// ---------------- 8) reduce partials ----------------
__global__ void k_stats() {
    int t = threadIdx.x;
    float s = 0.0f;
    for (int b = 0; b < RBLOCKS; b++) s += d_part[b * (2 * H) + t];
    d_sums[t] = s;
}

// ---------------- 9) BN + relu + residual ----------------
__global__ void k_fin(const float* x, const float* gamma,
                      const float* beta, float* out) {
    int idx = blockIdx.x * blockDim.x + threadIdx.x;
    if (idx < N_NODES * H) {
        int o = idx & 63;
        const float invN = 1.0f / (float)N_NODES;
        float mean = d_sums[o] * invN;
        float var  = d_sums[H + o] * invN - mean * mean;
        float istd = rsqrtf(var + 1e-5f);
        float v = out[idx];
        float bn = fmaf((v - mean) * istd, gamma[o], beta[o]);
        out[idx] = x[idx] + fmaxf(bn, 0.0f);
    }
}

extern "C" void kernel_launch(void* const* d_in, const int* in_sizes, int n_in,
                              void* d_out, int out_size) {
    const float* x     = (const float*)d_in[0];
    const float* ea    = (const float*)d_in[1];
    const int*   ei    = (const int*)d_in[2];
    const float* w1    = (const float*)d_in[3];
    const float* b1    = (const float*)d_in[4];
    const float* w2    = (const float*)d_in[5];
    const float* b2    = (const float*)d_in[6];
    const float* rw    = (const float*)d_in[7];
    const float* cb    = (const float*)d_in[8];
    const float* gamma = (const float*)d_in[9];
    const float* beta  = (const float*)d_in[10];
    float* out = (float*)d_out;

    k_zero_out<<<(N_NODES * H + 255) / 256, 256>>>(out);
    k_init<<<(EPAD + 255) / 256, 256>>>();
    k_prep<<<1, 64>>>(w1, b1);
    k_q<<<128, 128>>>(w1, b1, b2, w2);
    k_region<<<(N_EDGES + 255) / 256, 256>>>(ea);
    k_offsets<<<1, 32>>>();
    k_scatter<<<(N_EDGES + 255) / 256, 256>>>();
    k_msg<<<(EPAD + BLK_SLOTS - 1) / BLK_SLOTS, 128>>>(x, ea, ei, out);
    k_root<<<RBLOCKS, 256>>>(x, rw, cb, out);
    k_stats<<<1, 128>>>();
    k_fin<<<(N_NODES * H + 255) / 256, 256>>>(x, gamma, beta, out);
}

// round 9
// speedup vs baseline: 1.0144x; 1.0144x over previous
#include <cuda_runtime.h>

#define N_NODES 20000
#define N_EDGES 50000
#define H 64
#define HH 4096
#define NREG 65
#define GE 16
#define GROUPS 2
#define SUBIT 4
#define BLK_SLOTS (GROUPS * GE * SUBIT)   // 128 slots per k_msg block
#define EPAD (N_EDGES + NREG * GE)
#define NPB 32
#define RBLOCKS (N_NODES / NPB)           // 625 k_root blocks

// ---------------- scratch (static zero-init is load-bearing for run #1) ----
__device__ float d_Qbuf[NREG * 2 * HH];   // per region: Q0[4096] then Q1[4096]
__device__ int   d_regid[N_EDGES];
__device__ int   d_hist[NREG];            // zeroed by k_fin each run
__device__ int   d_cursor[NREG];          // zeroed by k_fin each run
__device__ int   d_sorted[EPAD];          // 0 = empty; stores eid+1
__device__ float d_agg[N_NODES * H];      // zeroed by k_fin each run
__device__ float d_sums[2 * H];           // zeroed by k_fin each run
__device__ unsigned d_ctr;                // last-block counter (self-resetting)

// ---- inline breakpoint prep: tbs (unsorted), sorted Bs, rankOf, idxOf -----
// Call from threads t < H after tbs filled & synced.
__device__ __forceinline__ float bp_of(const float* w1, const float* b1, int k) {
    float w = w1[k];
    return (w == 0.0f) ? 1e30f : (-b1[k] / w);
}

// ---------------- 0) region id + histogram + (last block) cursor offsets ---
__global__ void __launch_bounds__(256) k_region(const float* ea,
                                                const float* w1,
                                                const float* b1) {
    __shared__ float tbs[H];
    __shared__ float Bs[H];
    __shared__ int   bh[NREG];
    __shared__ int   isLast;
    int t = threadIdx.x;
    if (t < H) tbs[t] = bp_of(w1, b1, t);
    if (t < NREG) bh[t] = 0;
    __syncthreads();
    if (t < H) {
        float my = tbs[t];
        int rank = 0;
        for (int j = 0; j < H; j++) {
            float tj = tbs[j];
            rank += (tj < my) || (tj == my && j < t);
        }
        Bs[rank] = my;
    }
    __syncthreads();
    int e = blockIdx.x * blockDim.x + t;
    if (e < N_EDGES) {
        float a = ea[e];
        int r = 0;
        #pragma unroll 8
        for (int k = 0; k < H; k++) r += (Bs[k] <= a) ? 1 : 0;
        d_regid[e] = r;
        atomicAdd(&bh[r], 1);
    }
    __syncthreads();
    if (t < NREG && bh[t] > 0) atomicAdd(&d_hist[t], bh[t]);
    // last-block computes GE-aligned cursor offsets
    __threadfence();
    if (t == 0) {
        unsigned prev = atomicAdd(&d_ctr, 1u);
        isLast = (prev == gridDim.x - 1) ? 1 : 0;
    }
    __syncthreads();
    if (isLast && t == 0) {
        int s = 0;
        for (int r = 0; r < NREG; r++) {
            d_cursor[r] = s;
            s += (atomicAdd(&d_hist[r], 0) + (GE - 1)) & ~(GE - 1);
        }
        d_ctr = 0;
    }
}

// ---------------- 1) scatter edges into region-sorted list (eid+1) ---------
__global__ void k_scatter() {
    int e = blockIdx.x * blockDim.x + threadIdx.x;
    if (e < N_EDGES) {
        int r = d_regid[e];
        int pos = atomicAdd(&d_cursor[r], 1);
        d_sorted[pos] = e + 1;
    }
}

// ---------------- 2) Q0/Q1: 4 checkpoint chunks x rank-1 updates -----------
__global__ void __launch_bounds__(128) k_q(const float* w1, const float* b1,
                                           const float* b2, const float* w2) {
    __shared__ float w2sh[128][H + 1];
    __shared__ float tbs[H];
    __shared__ int   rankOf[H], idxOf[H];
    __shared__ float mb[H], mw[H], dB[H], dW[H];
    __shared__ int   cix[H];

    int t = threadIdx.x;
    int mg = blockIdx.x & 31, chunk = blockIdx.x >> 5;
    int r0 = chunk * 17;
    int rend = (r0 + 17 < NREG) ? r0 + 17 : NREG;
    int mbase = mg * 128;

    for (int i2 = t; i2 < 128 * H; i2 += 128) {
        int ml = i2 >> 6, k = i2 & 63;
        w2sh[ml][k] = w2[(mbase + ml) * H + k];
    }
    if (t < H) tbs[t] = bp_of(w1, b1, t);
    __syncthreads();
    if (t < H) {
        float my = tbs[t];
        int rank = 0;
        for (int j = 0; j < H; j++) {
            float tj = tbs[j];
            rank += (tj < my) || (tj == my && j < t);
        }
        rankOf[t] = rank;
        idxOf[rank] = t;
    }
    __syncthreads();
    if (t < H) {
        int k = t;
        float w = w1[k], b = b1[k];
        int rk = rankOf[k];
        bool act = (w > 0.0f) ? (rk < r0) : ((w < 0.0f) ? (rk >= r0) : (b > 0.0f));
        mb[k] = act ? b : 0.0f;
        mw[k] = act ? w : 0.0f;
        int kr = idxOf[t];
        float wr = w1[kr], br = b1[kr];
        float sgn = (wr > 0.0f) ? 1.0f : -1.0f;
        dB[t] = sgn * br;
        dW[t] = sgn * wr;
        cix[t] = kr;
    }
    __syncthreads();

    int m = mbase + t;
    const float* row = w2sh[t];
    float q0 = b2[m];
    float q1 = 0.0f;
    #pragma unroll 8
    for (int k = 0; k < H; k++) {
        float v = row[k];
        q0 = fmaf(mb[k], v, q0);
        q1 = fmaf(mw[k], v, q1);
    }
    for (int r = r0; r < rend; r++) {
        d_Qbuf[r * (2 * HH) + m]      = q0;
        d_Qbuf[r * (2 * HH) + HH + m] = q1;
        if (r < H) {
            float v = row[cix[r]];
            q0 = fmaf(dB[r], v, q0);
            q1 = fmaf(dW[r], v, q1);
        }
    }
}

// ---------------- 3) message + scatter-add into d_agg (hot; PROFILED) ------
__global__ void __launch_bounds__(128) k_msg(const float* x, const float* ea,
                                             const int* ei) {
    __shared__ float xs[GROUPS][GE][H];
    __shared__ float sa[GROUPS][GE];
    __shared__ int   sdst[GROUPS][GE];
    __shared__ int   ssrc[GROUPS][GE];
    __shared__ int   sreg[GROUPS][GE];

    int g = threadIdx.x >> 6;
    int o = threadIdx.x & 63;
    int blockBase = blockIdx.x * BLK_SLOTS;

    for (int it = 0; it < SUBIT; it++) {
        int sbase = blockBase + (it * GROUPS + g) * GE;
        __syncthreads();
        if (o < GE) {
            int slot = sbase + o;
            int eid1 = (slot < EPAD) ? d_sorted[slot] : 0;
            int src = -1, dst = 0, r = -1;
            float a = 0.0f;
            if (eid1 > 0) {
                int eid = eid1 - 1;
                a = ea[eid];
                src = ei[eid];
                dst = ei[N_EDGES + eid];
                r = d_regid[eid];
                if (src < 0 || src >= N_NODES || dst < 0 || dst >= N_NODES) {
                    src = -1; dst = 0;
                }
            }
            sa[g][o] = a; ssrc[g][o] = src; sdst[g][o] = dst; sreg[g][o] = r;
        }
        __syncthreads();
        int rr = -1;
        #pragma unroll
        for (int j = 0; j < GE; j++) {
            int s = ssrc[g][j];
            xs[g][j][o] = (s >= 0) ? x[s * H + o] : 0.0f;
            int rg = sreg[g][j];
            rr = (rg > rr) ? rg : rr;
        }
        __syncthreads();
        if (rr >= 0) {
            int q0base = rr * (2 * HH);
            int q1base = q0base + HH;
            float acc0[GE], acc1[GE];
            #pragma unroll
            for (int j = 0; j < GE; j++) { acc0[j] = 0.0f; acc1[j] = 0.0f; }
            #pragma unroll 4
            for (int i = 0; i < H; i++) {
                float q0 = d_Qbuf[q0base + i * H + o];
                float q1 = d_Qbuf[q1base + i * H + o];
                #pragma unroll
                for (int j = 0; j < GE; j++) {
                    float xv = xs[g][j][i];
                    acc0[j] = fmaf(xv, q0, acc0[j]);
                    acc1[j] = fmaf(xv, q1, acc1[j]);
                }
            }
            #pragma unroll
            for (int j = 0; j < GE; j++) {
                if (ssrc[g][j] >= 0) {
                    atomicAdd(&d_agg[sdst[g][j] * H + o],
                              fmaf(sa[g][j], acc1[j], acc0[j]));
                }
            }
        }
    }
}

// ---------------- 4) root GEMM + bias + agg; BN sums via spread atomics ----
__global__ void __launch_bounds__(256) k_root(const float* x, const float* rw,
                                              const float* cb, float* out) {
    __shared__ float rws[HH];
    __shared__ float xrs[4][H];
    __shared__ float red[256];
    int t = threadIdx.x;
    for (int idx = t; idx < HH; idx += 256) {
        int oo = idx >> 6, ii = idx & 63;
        rws[ii * H + oo] = rw[idx];
    }
    int o = t & 63, nl = t >> 6;
    __syncthreads();
    float cbo = cb[o];
    float psum = 0.0f, psq = 0.0f;
    int n0 = blockIdx.x * NPB;
    for (int c = 0; c < NPB; c += 4) {
        int n = n0 + c + nl;
        xrs[nl][o] = x[n * H + o];
        __syncthreads();
        float acc = 0.0f;
        #pragma unroll 8
        for (int i = 0; i < H; i++) acc = fmaf(xrs[nl][i], rws[i * H + o], acc);
        float val = acc + d_agg[n * H + o] + cbo;
        out[n * H + o] = val;
        psum += val;
        psq = fmaf(val, val, psq);
        __syncthreads();
    }
    red[t] = psum; __syncthreads();
    if (nl < 2) red[t] += red[t + 128];
    __syncthreads();
    if (nl == 0) atomicAdd(&d_sums[o], red[t] + red[t + 64]);
    __syncthreads();
    red[t] = psq; __syncthreads();
    if (nl < 2) red[t] += red[t + 128];
    __syncthreads();
    if (nl == 0) atomicAdd(&d_sums[H + o], red[t] + red[t + 64]);
}

// ---------------- 5) BN + relu + residual, then reset scratch for replay ---
__global__ void k_fin(const float* x, const float* gamma,
                      const float* beta, float* out) {
    int idx = blockIdx.x * blockDim.x + threadIdx.x;
    if (idx < N_NODES * H) {
        int o = idx & 63;
        const float invN = 1.0f / (float)N_NODES;
        float mean = d_sums[o] * invN;
        float var  = d_sums[H + o] * invN - mean * mean;
        float istd = rsqrtf(var + 1e-5f);
        float v = out[idx];
        float bn = fmaf((v - mean) * istd, gamma[o], beta[o]);
        out[idx] = x[idx] + fmaxf(bn, 0.0f);
        // housekeeping for the next graph replay
        d_agg[idx] = 0.0f;
        if (idx < EPAD) d_sorted[idx] = 0;
        if (idx < NREG) { d_hist[idx] = 0; d_cursor[idx] = 0; }
    }
}

// separate tiny reset for d_sums AFTER all k_fin blocks read it is unsafe
// within one kernel; instead reset it from k_fin block 0 is racy. Use a
// dedicated trailing thread block inside k_fin? Simplest safe approach:
// reset d_sums in k_region of the NEXT run before anyone reads it — but
// k_root atomically accumulates. So: zero d_sums at the START of k_root
// run is racy too. Dedicated zeroing in k_scatter (runs before k_root,
// after k_region, does not touch d_sums consumers):
__global__ void k_scatter_and_zero() {
    int e = blockIdx.x * blockDim.x + threadIdx.x;
    if (e < 2 * H) d_sums[e] = 0.0f;
    if (e < N_EDGES) {
        int r = d_regid[e];
        int pos = atomicAdd(&d_cursor[r], 1);
        d_sorted[pos] = e + 1;
    }
}

extern "C" void kernel_launch(void* const* d_in, const int* in_sizes, int n_in,
                              void* d_out, int out_size) {
    const float* x     = (const float*)d_in[0];
    const float* ea    = (const float*)d_in[1];
    const int*   ei    = (const int*)d_in[2];
    const float* w1    = (const float*)d_in[3];
    const float* b1    = (const float*)d_in[4];
    const float* w2    = (const float*)d_in[5];
    const float* b2    = (const float*)d_in[6];
    const float* rw    = (const float*)d_in[7];
    const float* cb    = (const float*)d_in[8];
    const float* gamma = (const float*)d_in[9];
    const float* beta  = (const float*)d_in[10];
    float* out = (float*)d_out;

    k_region<<<(N_EDGES + 255) / 256, 256>>>(ea, w1, b1);
    k_scatter_and_zero<<<(N_EDGES + 255) / 256, 256>>>();
    k_q<<<128, 128>>>(w1, b1, b2, w2);
    k_msg<<<(EPAD + BLK_SLOTS - 1) / BLK_SLOTS, 128>>>(x, ea, ei);  // profiled slot
    k_root<<<RBLOCKS, 256>>>(x, rw, cb, out);
    k_fin<<<(N_NODES * H + 255) / 256, 256>>>(x, gamma, beta, out);
}

// round 10
// speedup vs baseline: 1.0567x; 1.0417x over previous
#include <cuda_runtime.h>

#define N_NODES 20000
#define N_EDGES 50000
#define H 64
#define HH 4096
#define NREG 65
#define GE 16
#define GROUPS 2
#define SUBIT 4
#define BLK_SLOTS (GROUPS * GE * SUBIT)   // 128 slots per k_msg block
#define EPAD (N_EDGES + NREG * GE)
#define NPB 32
#define RBLOCKS (N_NODES / NPB)           // 625 k_root blocks

// ---------------- scratch (static zero-init is load-bearing for run #1) ----
// d_Qbuf per region r: Q0 pair-permuted at [r*2HH + (i>>1)*128 + 2*o + (i&1)],
// Q1 same at +HH  => {Q[2c][o], Q[2c+1][o]} is one aligned float2.
__device__ __align__(16) float d_Qbuf[NREG * 2 * HH];
__device__ int   d_regid[N_EDGES];
__device__ int   d_hist[NREG];            // zeroed by k_fin each run
__device__ int   d_cursor[NREG];          // zeroed by k_fin each run
__device__ int   d_sorted[EPAD];          // 0 = empty; stores eid+1
__device__ __align__(16) float d_agg[N_NODES * H];   // zeroed by k_fin
__device__ float d_sums[2 * H];           // zeroed in k_scatter_and_zero
__device__ unsigned d_ctr;                // last-block counter (self-resetting)

__device__ __forceinline__ float bp_of(const float* w1, const float* b1, int k) {
    float w = w1[k];
    return (w == 0.0f) ? 1e30f : (-b1[k] / w);
}

// ---------------- 0) region id + histogram + (last block) cursor offsets ---
__global__ void __launch_bounds__(256) k_region(const float* ea,
                                                const float* w1,
                                                const float* b1) {
    __shared__ float tbs[H];
    __shared__ float Bs[H];
    __shared__ int   bh[NREG];
    __shared__ int   isLast;
    int t = threadIdx.x;
    if (t < H) tbs[t] = bp_of(w1, b1, t);
    if (t < NREG) bh[t] = 0;
    __syncthreads();
    if (t < H) {
        float my = tbs[t];
        int rank = 0;
        for (int j = 0; j < H; j++) {
            float tj = tbs[j];
            rank += (tj < my) || (tj == my && j < t);
        }
        Bs[rank] = my;
    }
    __syncthreads();
    int e = blockIdx.x * blockDim.x + t;
    if (e < N_EDGES) {
        float a = ea[e];
        int r = 0;
        #pragma unroll 8
        for (int k = 0; k < H; k++) r += (Bs[k] <= a) ? 1 : 0;
        d_regid[e] = r;
        atomicAdd(&bh[r], 1);
    }
    __syncthreads();
    if (t < NREG && bh[t] > 0) atomicAdd(&d_hist[t], bh[t]);
    __threadfence();
    if (t == 0) {
        unsigned prev = atomicAdd(&d_ctr, 1u);
        isLast = (prev == gridDim.x - 1) ? 1 : 0;
    }
    __syncthreads();
    if (isLast && t == 0) {
        int s = 0;
        for (int r = 0; r < NREG; r++) {
            d_cursor[r] = s;
            s += (atomicAdd(&d_hist[r], 0) + (GE - 1)) & ~(GE - 1);
        }
        d_ctr = 0;
    }
}

// ---------------- 1) scatter (+ zero d_sums for this run) ----------------
__global__ void k_scatter_and_zero() {
    int e = blockIdx.x * blockDim.x + threadIdx.x;
    if (e < 2 * H) d_sums[e] = 0.0f;
    if (e < N_EDGES) {
        int r = d_regid[e];
        int pos = atomicAdd(&d_cursor[r], 1);
        d_sorted[pos] = e + 1;
    }
}

// ---------------- 2) Q0/Q1: 4 checkpoint chunks x rank-1 updates -----------
__global__ void __launch_bounds__(128) k_q(const float* w1, const float* b1,
                                           const float* b2, const float* w2) {
    __shared__ float w2sh[128][H + 1];
    __shared__ float tbs[H];
    __shared__ int   rankOf[H], idxOf[H];
    __shared__ float mb[H], mw[H], dB[H], dW[H];
    __shared__ int   cix[H];

    int t = threadIdx.x;
    int mg = blockIdx.x & 31, chunk = blockIdx.x >> 5;
    int r0 = chunk * 17;
    int rend = (r0 + 17 < NREG) ? r0 + 17 : NREG;
    int mbase = mg * 128;

    for (int i2 = t; i2 < 128 * H; i2 += 128) {
        int ml = i2 >> 6, k = i2 & 63;
        w2sh[ml][k] = w2[(mbase + ml) * H + k];
    }
    if (t < H) tbs[t] = bp_of(w1, b1, t);
    __syncthreads();
    if (t < H) {
        float my = tbs[t];
        int rank = 0;
        for (int j = 0; j < H; j++) {
            float tj = tbs[j];
            rank += (tj < my) || (tj == my && j < t);
        }
        rankOf[t] = rank;
        idxOf[rank] = t;
    }
    __syncthreads();
    if (t < H) {
        int k = t;
        float w = w1[k], b = b1[k];
        int rk = rankOf[k];
        bool act = (w > 0.0f) ? (rk < r0) : ((w < 0.0f) ? (rk >= r0) : (b > 0.0f));
        mb[k] = act ? b : 0.0f;
        mw[k] = act ? w : 0.0f;
        int kr = idxOf[t];
        float wr = w1[kr], br = b1[kr];
        float sgn = (wr > 0.0f) ? 1.0f : -1.0f;
        dB[t] = sgn * br;
        dW[t] = sgn * wr;
        cix[t] = kr;
    }
    __syncthreads();

    int m = mbase + t;
    int i = m >> 6, o = m & 63;
    int p = (i >> 1) * 128 + 2 * o + (i & 1);   // pair-permuted index
    const float* row = w2sh[t];
    float q0 = b2[m];
    float q1 = 0.0f;
    #pragma unroll 8
    for (int k = 0; k < H; k++) {
        float v = row[k];
        q0 = fmaf(mb[k], v, q0);
        q1 = fmaf(mw[k], v, q1);
    }
    for (int r = r0; r < rend; r++) {
        d_Qbuf[r * (2 * HH) + p]      = q0;
        d_Qbuf[r * (2 * HH) + HH + p] = q1;
        if (r < H) {
            float v = row[cix[r]];
            q0 = fmaf(dB[r], v, q0);
            q1 = fmaf(dW[r], v, q1);
        }
    }
}

// ---------------- 3) message + scatter-add (hot; float2-paired) ------------
__global__ void __launch_bounds__(128, 6) k_msg(const float* x, const float* ea,
                                                const int* ei) {
    __shared__ float2 xs[GROUPS][GE][32];   // {x[2c], x[2c+1]} per edge
    __shared__ float  sa[GROUPS][GE];
    __shared__ int    ssrc[GROUPS][GE];
    __shared__ int    sdst[GROUPS][GE];
    __shared__ int    sreg[GROUPS][GE];

    int g = threadIdx.x >> 6;
    int o = threadIdx.x & 63;
    int blockBase = blockIdx.x * BLK_SLOTS;

    for (int it = 0; it < SUBIT; it++) {
        int sbase = blockBase + (it * GROUPS + g) * GE;
        __syncthreads();
        if (o < GE) {
            int slot = sbase + o;
            int eid1 = (slot < EPAD) ? d_sorted[slot] : 0;
            int src = -1, dst = 0, r = -1;
            float a = 0.0f;
            if (eid1 > 0) {
                int eid = eid1 - 1;
                a = ea[eid];
                src = ei[eid];
                dst = ei[N_EDGES + eid];
                r = d_regid[eid];
                if (src < 0 || src >= N_NODES || dst < 0 || dst >= N_NODES) {
                    src = -1; dst = 0;
                }
            }
            sa[g][o] = a; ssrc[g][o] = src; sdst[g][o] = dst; sreg[g][o] = r;
        }
        __syncthreads();
        int rr = -1;
        #pragma unroll
        for (int j = 0; j < GE; j++) { int rg = sreg[g][j]; rr = (rg > rr) ? rg : rr; }
        // stage x as float2 pairs: thread handles (j = 2*jj + o>>5, c = o&31)
        {
            int c = o & 31, jh = o >> 5;
            #pragma unroll
            for (int jj = 0; jj < GE / 2; jj++) {
                int j = jj * 2 + jh;
                int s = ssrc[g][j];
                float2 v = make_float2(0.0f, 0.0f);
                if (s >= 0) v = *reinterpret_cast<const float2*>(x + s * H + 2 * c);
                xs[g][j][c] = v;
            }
        }
        __syncthreads();
        if (rr >= 0) {
            const float* Q0 = d_Qbuf + rr * (2 * HH);
            const float* Q1 = Q0 + HH;
            float acc0[GE], acc1[GE];
            #pragma unroll
            for (int j = 0; j < GE; j++) { acc0[j] = 0.0f; acc1[j] = 0.0f; }
            #pragma unroll 4
            for (int c = 0; c < 32; c++) {
                float2 q0 = *reinterpret_cast<const float2*>(Q0 + c * 128 + 2 * o);
                float2 q1 = *reinterpret_cast<const float2*>(Q1 + c * 128 + 2 * o);
                #pragma unroll
                for (int j = 0; j < GE; j++) {
                    float2 xv = xs[g][j][c];
                    acc0[j] = fmaf(xv.x, q0.x, acc0[j]);
                    acc0[j] = fmaf(xv.y, q0.y, acc0[j]);
                    acc1[j] = fmaf(xv.x, q1.x, acc1[j]);
                    acc1[j] = fmaf(xv.y, q1.y, acc1[j]);
                }
            }
            #pragma unroll
            for (int j = 0; j < GE; j++) {
                bool live = (ssrc[g][j] >= 0);
                float v = live ? fmaf(sa[g][j], acc1[j], acc0[j]) : 0.0f;
                float vh = __shfl_down_sync(0xFFFFFFFF, v, 1);
                if (live && (o & 1) == 0) {
                    float* p = d_agg + sdst[g][j] * H + o;
                    asm volatile("red.global.add.v2.f32 [%0], {%1, %2};"
                                 :: "l"(p), "f"(v), "f"(vh) : "memory");
                }
            }
        }
    }
}

// ---------------- 4) root GEMM + bias + agg; BN sums via spread atomics ----
__global__ void __launch_bounds__(256) k_root(const float* x, const float* rw,
                                              const float* cb, float* out) {
    __shared__ float rws[HH];
    __shared__ float xrs[4][H];
    __shared__ float red[256];
    int t = threadIdx.x;
    for (int idx = t; idx < HH; idx += 256) {
        int oo = idx >> 6, ii = idx & 63;
        rws[ii * H + oo] = rw[idx];
    }
    int o = t & 63, nl = t >> 6;
    __syncthreads();
    float cbo = cb[o];
    float psum = 0.0f, psq = 0.0f;
    int n0 = blockIdx.x * NPB;
    for (int c = 0; c < NPB; c += 4) {
        int n = n0 + c + nl;
        xrs[nl][o] = x[n * H + o];
        __syncthreads();
        float acc = 0.0f;
        #pragma unroll 8
        for (int i = 0; i < H; i++) acc = fmaf(xrs[nl][i], rws[i * H + o], acc);
        float val = acc + d_agg[n * H + o] + cbo;
        out[n * H + o] = val;
        psum += val;
        psq = fmaf(val, val, psq);
        __syncthreads();
    }
    red[t] = psum; __syncthreads();
    if (nl < 2) red[t] += red[t + 128];
    __syncthreads();
    if (nl == 0) atomicAdd(&d_sums[o], red[t] + red[t + 64]);
    __syncthreads();
    red[t] = psq; __syncthreads();
    if (nl < 2) red[t] += red[t + 128];
    __syncthreads();
    if (nl == 0) atomicAdd(&d_sums[H + o], red[t] + red[t + 64]);
}

// ---------------- 5) BN + relu + residual, then reset scratch for replay ---
__global__ void k_fin(const float* x, const float* gamma,
                      const float* beta, float* out) {
    int idx = blockIdx.x * blockDim.x + threadIdx.x;
    if (idx < N_NODES * H) {
        int o = idx & 63;
        const float invN = 1.0f / (float)N_NODES;
        float mean = d_sums[o] * invN;
        float var  = d_sums[H + o] * invN - mean * mean;
        float istd = rsqrtf(var + 1e-5f);
        float v = out[idx];
        float bn = fmaf((v - mean) * istd, gamma[o], beta[o]);
        out[idx] = x[idx] + fmaxf(bn, 0.0f);
        // housekeeping for the next graph replay
        d_agg[idx] = 0.0f;
        if (idx < EPAD) d_sorted[idx] = 0;
        if (idx < NREG) { d_hist[idx] = 0; d_cursor[idx] = 0; }
    }
}

extern "C" void kernel_launch(void* const* d_in, const int* in_sizes, int n_in,
                              void* d_out, int out_size) {
    const float* x     = (const float*)d_in[0];
    const float* ea    = (const float*)d_in[1];
    const int*   ei    = (const int*)d_in[2];
    const float* w1    = (const float*)d_in[3];
    const float* b1    = (const float*)d_in[4];
    const float* w2    = (const float*)d_in[5];
    const float* b2    = (const float*)d_in[6];
    const float* rw    = (const float*)d_in[7];
    const float* cb    = (const float*)d_in[8];
    const float* gamma = (const float*)d_in[9];
    const float* beta  = (const float*)d_in[10];
    float* out = (float*)d_out;

    k_region<<<(N_EDGES + 255) / 256, 256>>>(ea, w1, b1);
    k_scatter_and_zero<<<(N_EDGES + 255) / 256, 256>>>();
    k_q<<<128, 128>>>(w1, b1, b2, w2);
    k_msg<<<(EPAD + BLK_SLOTS - 1) / BLK_SLOTS, 128>>>(x, ea, ei);  // profiled slot
    k_root<<<RBLOCKS, 256>>>(x, rw, cb, out);
    k_fin<<<(N_NODES * H + 255) / 256, 256>>>(x, gamma, beta, out);
}

// round 11
// speedup vs baseline: 1.1423x; 1.0810x over previous
#include <cuda_runtime.h>

#define N_NODES 20000
#define N_EDGES 50000
#define H 64
#define HH 4096
#define NREG 65
#define GE 16
#define GROUPS 2
#define BLK_SLOTS (GROUPS * GE)           // 32 slots per k_msg block
#define EPAD (N_EDGES + NREG * GE)
#define NPB 32
#define RBLOCKS (N_NODES / NPB)           // 625 k_root blocks

// ---------------- scratch (static zero-init is load-bearing for run #1) ----
__device__ __align__(16) float d_Qbuf[NREG * 2 * HH];  // plain: Q0[i*H+o], Q1 at +HH
__device__ int   d_regid[N_EDGES];
__device__ int   d_hist[NREG];            // zeroed by k_fin each run
__device__ int   d_cursor[NREG];          // zeroed by k_fin each run
__device__ int   d_sorted[EPAD];          // 0 = empty; stores eid+1
__device__ __align__(16) float d_agg[N_NODES * H];   // zeroed by k_fin
__device__ float d_sums[2 * H];           // zeroed in k_scatter_and_zero
__device__ unsigned d_ctr;                // last-block counter (self-resetting)

__device__ __forceinline__ float bp_of(const float* w1, const float* b1, int k) {
    float w = w1[k];
    return (w == 0.0f) ? 1e30f : (-b1[k] / w);
}

// ---------------- 0) region id + histogram + (last block) cursor offsets ---
__global__ void __launch_bounds__(256) k_region(const float* ea,
                                                const float* w1,
                                                const float* b1) {
    __shared__ float tbs[H];
    __shared__ float Bs[H];
    __shared__ int   bh[NREG];
    __shared__ int   isLast;
    int t = threadIdx.x;
    if (t < H) tbs[t] = bp_of(w1, b1, t);
    if (t < NREG) bh[t] = 0;
    __syncthreads();
    if (t < H) {
        float my = tbs[t];
        int rank = 0;
        for (int j = 0; j < H; j++) {
            float tj = tbs[j];
            rank += (tj < my) || (tj == my && j < t);
        }
        Bs[rank] = my;
    }
    __syncthreads();
    int e = blockIdx.x * blockDim.x + t;
    if (e < N_EDGES) {
        float a = ea[e];
        int r = 0;
        #pragma unroll 8
        for (int k = 0; k < H; k++) r += (Bs[k] <= a) ? 1 : 0;
        d_regid[e] = r;
        atomicAdd(&bh[r], 1);
    }
    __syncthreads();
    if (t < NREG && bh[t] > 0) atomicAdd(&d_hist[t], bh[t]);
    __threadfence();
    if (t == 0) {
        unsigned prev = atomicAdd(&d_ctr, 1u);
        isLast = (prev == gridDim.x - 1) ? 1 : 0;
    }
    __syncthreads();
    if (isLast && t == 0) {
        int s = 0;
        for (int r = 0; r < NREG; r++) {
            d_cursor[r] = s;
            s += (atomicAdd(&d_hist[r], 0) + (GE - 1)) & ~(GE - 1);
        }
        d_ctr = 0;
    }
}

// ---------------- 1) scatter (+ zero d_sums for this run) ----------------
__global__ void k_scatter_and_zero() {
    int e = blockIdx.x * blockDim.x + threadIdx.x;
    if (e < 2 * H) d_sums[e] = 0.0f;
    if (e < N_EDGES) {
        int r = d_regid[e];
        int pos = atomicAdd(&d_cursor[r], 1);
        d_sorted[pos] = e + 1;
    }
}

// ---------------- 2) Q0/Q1: 4 checkpoint chunks x rank-1 updates -----------
__global__ void __launch_bounds__(128) k_q(const float* w1, const float* b1,
                                           const float* b2, const float* w2) {
    __shared__ float w2sh[128][H + 1];
    __shared__ float tbs[H];
    __shared__ int   rankOf[H], idxOf[H];
    __shared__ float mb[H], mw[H], dB[H], dW[H];
    __shared__ int   cix[H];

    int t = threadIdx.x;
    int mg = blockIdx.x & 31, chunk = blockIdx.x >> 5;
    int r0 = chunk * 17;
    int rend = (r0 + 17 < NREG) ? r0 + 17 : NREG;
    int mbase = mg * 128;

    for (int i2 = t; i2 < 128 * H; i2 += 128) {
        int ml = i2 >> 6, k = i2 & 63;
        w2sh[ml][k] = w2[(mbase + ml) * H + k];
    }
    if (t < H) tbs[t] = bp_of(w1, b1, t);
    __syncthreads();
    if (t < H) {
        float my = tbs[t];
        int rank = 0;
        for (int j = 0; j < H; j++) {
            float tj = tbs[j];
            rank += (tj < my) || (tj == my && j < t);
        }
        rankOf[t] = rank;
        idxOf[rank] = t;
    }
    __syncthreads();
    if (t < H) {
        int k = t;
        float w = w1[k], b = b1[k];
        int rk = rankOf[k];
        bool act = (w > 0.0f) ? (rk < r0) : ((w < 0.0f) ? (rk >= r0) : (b > 0.0f));
        mb[k] = act ? b : 0.0f;
        mw[k] = act ? w : 0.0f;
        int kr = idxOf[t];
        float wr = w1[kr], br = b1[kr];
        float sgn = (wr > 0.0f) ? 1.0f : -1.0f;
        dB[t] = sgn * br;
        dW[t] = sgn * wr;
        cix[t] = kr;
    }
    __syncthreads();

    int m = mbase + t;
    const float* row = w2sh[t];
    float q0 = b2[m];
    float q1 = 0.0f;
    #pragma unroll 8
    for (int k = 0; k < H; k++) {
        float v = row[k];
        q0 = fmaf(mb[k], v, q0);
        q1 = fmaf(mw[k], v, q1);
    }
    for (int r = r0; r < rend; r++) {
        d_Qbuf[r * (2 * HH) + m]      = q0;
        d_Qbuf[r * (2 * HH) + HH + m] = q1;
        if (r < H) {
            float v = row[cix[r]];
            q0 = fmaf(dB[r], v, q0);
            q1 = fmaf(dW[r], v, q1);
        }
    }
}

// ---------------- 3) message + scatter-add (hot; 1 batch/block) ------------
__global__ void __launch_bounds__(128, 6) k_msg(const float* x, const float* ea,
                                                const int* ei) {
    __shared__ float xs[GROUPS][GE][H];
    __shared__ float sa[GROUPS][GE];
    __shared__ int   ssrc[GROUPS][GE];
    __shared__ int   sdst[GROUPS][GE];
    __shared__ int   sreg[GROUPS][GE];

    int g = threadIdx.x >> 6;
    int o = threadIdx.x & 63;
    int sbase = blockIdx.x * BLK_SLOTS + g * GE;

    if (o < GE) {
        int slot = sbase + o;
        int eid1 = (slot < EPAD) ? d_sorted[slot] : 0;
        int src = -1, dst = 0, r = -1;
        float a = 0.0f;
        if (eid1 > 0) {
            int eid = eid1 - 1;
            a = ea[eid];
            src = ei[eid];
            dst = ei[N_EDGES + eid];
            r = d_regid[eid];
            if (src < 0 || src >= N_NODES || dst < 0 || dst >= N_NODES) {
                src = -1; dst = 0;
            }
        }
        sa[g][o] = a; ssrc[g][o] = src; sdst[g][o] = dst; sreg[g][o] = r;
    }
    __syncthreads();
    int rr = -1;
    #pragma unroll
    for (int j = 0; j < GE; j++) {
        int s = ssrc[g][j];
        xs[g][j][o] = (s >= 0) ? x[s * H + o] : 0.0f;
        int rg = sreg[g][j];
        rr = (rg > rr) ? rg : rr;
    }
    __syncthreads();
    if (rr < 0) return;

    const float* Q0 = d_Qbuf + rr * (2 * HH);
    const float* Q1 = Q0 + HH;
    float acc0[GE], acc1[GE];
    #pragma unroll
    for (int j = 0; j < GE; j++) { acc0[j] = 0.0f; acc1[j] = 0.0f; }
    #pragma unroll 4
    for (int i = 0; i < H; i++) {
        float q0 = Q0[i * H + o];
        float q1 = Q1[i * H + o];
        #pragma unroll
        for (int j = 0; j < GE; j++) {
            float xv = xs[g][j][i];
            acc0[j] = fmaf(xv, q0, acc0[j]);
            acc1[j] = fmaf(xv, q1, acc1[j]);
        }
    }
    #pragma unroll
    for (int j = 0; j < GE; j++) {
        bool live = (ssrc[g][j] >= 0);
        float v = live ? fmaf(sa[g][j], acc1[j], acc0[j]) : 0.0f;
        float vh = __shfl_down_sync(0xFFFFFFFF, v, 1);
        if (live && (o & 1) == 0) {
            float* p = d_agg + sdst[g][j] * H + o;
            asm volatile("red.global.add.v2.f32 [%0], {%1, %2};"
                         :: "l"(p), "f"(v), "f"(vh) : "memory");
        }
    }
}

// ---------------- 4) root GEMM + bias + agg; BN sums via spread atomics ----
__global__ void __launch_bounds__(256) k_root(const float* x, const float* rw,
                                              const float* cb, float* out) {
    __shared__ float rws[HH];
    __shared__ float xrs[4][H];
    __shared__ float red[256];
    int t = threadIdx.x;
    for (int idx = t; idx < HH; idx += 256) {
        int oo = idx >> 6, ii = idx & 63;
        rws[ii * H + oo] = rw[idx];
    }
    int o = t & 63, nl = t >> 6;
    __syncthreads();
    float cbo = cb[o];
    float psum = 0.0f, psq = 0.0f;
    int n0 = blockIdx.x * NPB;
    for (int c = 0; c < NPB; c += 4) {
        int n = n0 + c + nl;
        xrs[nl][o] = x[n * H + o];
        __syncthreads();
        float acc = 0.0f;
        #pragma unroll 8
        for (int i = 0; i < H; i++) acc = fmaf(xrs[nl][i], rws[i * H + o], acc);
        float val = acc + d_agg[n * H + o] + cbo;
        out[n * H + o] = val;
        psum += val;
        psq = fmaf(val, val, psq);
        __syncthreads();
    }
    red[t] = psum; __syncthreads();
    if (nl < 2) red[t] += red[t + 128];
    __syncthreads();
    if (nl == 0) atomicAdd(&d_sums[o], red[t] + red[t + 64]);
    __syncthreads();
    red[t] = psq; __syncthreads();
    if (nl < 2) red[t] += red[t + 128];
    __syncthreads();
    if (nl == 0) atomicAdd(&d_sums[H + o], red[t] + red[t + 64]);
}

// ---------------- 5) BN + relu + residual, then reset scratch for replay ---
__global__ void k_fin(const float* x, const float* gamma,
                      const float* beta, float* out) {
    int idx = blockIdx.x * blockDim.x + threadIdx.x;
    if (idx < N_NODES * H) {
        int o = idx & 63;
        const float invN = 1.0f / (float)N_NODES;
        float mean = d_sums[o] * invN;
        float var  = d_sums[H + o] * invN - mean * mean;
        float istd = rsqrtf(var + 1e-5f);
        float v = out[idx];
        float bn = fmaf((v - mean) * istd, gamma[o], beta[o]);
        out[idx] = x[idx] + fmaxf(bn, 0.0f);
        // housekeeping for the next graph replay
        d_agg[idx] = 0.0f;
        if (idx < EPAD) d_sorted[idx] = 0;
        if (idx < NREG) { d_hist[idx] = 0; d_cursor[idx] = 0; }
    }
}

extern "C" void kernel_launch(void* const* d_in, const int* in_sizes, int n_in,
                              void* d_out, int out_size) {
    const float* x     = (const float*)d_in[0];
    const float* ea    = (const float*)d_in[1];
    const int*   ei    = (const int*)d_in[2];
    const float* w1    = (const float*)d_in[3];
    const float* b1    = (const float*)d_in[4];
    const float* w2    = (const float*)d_in[5];
    const float* b2    = (const float*)d_in[6];
    const float* rw    = (const float*)d_in[7];
    const float* cb    = (const float*)d_in[8];
    const float* gamma = (const float*)d_in[9];
    const float* beta  = (const float*)d_in[10];
    float* out = (float*)d_out;

    k_region<<<(N_EDGES + 255) / 256, 256>>>(ea, w1, b1);
    k_scatter_and_zero<<<(N_EDGES + 255) / 256, 256>>>();
    k_q<<<128, 128>>>(w1, b1, b2, w2);
    k_msg<<<(EPAD + BLK_SLOTS - 1) / BLK_SLOTS, 128>>>(x, ea, ei);  // profiled slot
    k_root<<<RBLOCKS, 256>>>(x, rw, cb, out);
    k_fin<<<(N_NODES * H + 255) / 256, 256>>>(x, gamma, beta, out);
}

// round 12
// speedup vs baseline: 1.1935x; 1.0449x over previous
#include <cuda_runtime.h>

#define N_NODES 20000
#define N_EDGES 50000
#define H 64
#define HH 4096
#define NREG 65
#define GE 8
#define WARPS 4
#define BLK_SLOTS (WARPS * GE)            // 32 edges per k_msg block
#define EPAD (N_EDGES + NREG * GE)
#define NPB 32
#define RBLOCKS (N_NODES / NPB)           // 625 k_root blocks

// ---------------- scratch (static zero-init is load-bearing for run #1) ----
// d_Qbuf per region r: PAIR-PERMUTED: Q0 at [r*2HH + (i>>1)*128 + 2*o + (i&1)],
// Q1 at +HH  => {Q[2c][o], Q[2c+1][o]} is one aligned float2.
__device__ __align__(16) float d_Qbuf[NREG * 2 * HH];
__device__ int   d_regid[N_EDGES];
__device__ int   d_hist[NREG];            // zeroed by k_fin each run
__device__ int   d_cursor[NREG];          // zeroed by k_fin each run
__device__ int   d_sorted[EPAD];          // 0 = empty; stores eid+1
__device__ __align__(16) float d_agg[N_NODES * H];   // zeroed by k_fin
__device__ float d_sums[2 * H];           // zeroed in k_scatter_and_zero
__device__ unsigned d_ctr;                // last-block counter (self-resetting)

__device__ __forceinline__ float bp_of(const float* w1, const float* b1, int k) {
    float w = w1[k];
    return (w == 0.0f) ? 1e30f : (-b1[k] / w);
}

// ---------------- 0) region id + histogram + (last block) cursor offsets ---
__global__ void __launch_bounds__(256) k_region(const float* ea,
                                                const float* w1,
                                                const float* b1) {
    __shared__ float tbs[H];
    __shared__ float Bs[H];
    __shared__ int   bh[NREG];
    __shared__ int   isLast;
    int t = threadIdx.x;
    if (t < H) tbs[t] = bp_of(w1, b1, t);
    if (t < NREG) bh[t] = 0;
    __syncthreads();
    if (t < H) {
        float my = tbs[t];
        int rank = 0;
        for (int j = 0; j < H; j++) {
            float tj = tbs[j];
            rank += (tj < my) || (tj == my && j < t);
        }
        Bs[rank] = my;
    }
    __syncthreads();
    int e = blockIdx.x * blockDim.x + t;
    if (e < N_EDGES) {
        float a = ea[e];
        int r = 0;
        #pragma unroll 8
        for (int k = 0; k < H; k++) r += (Bs[k] <= a) ? 1 : 0;
        d_regid[e] = r;
        atomicAdd(&bh[r], 1);
    }
    __syncthreads();
    if (t < NREG && bh[t] > 0) atomicAdd(&d_hist[t], bh[t]);
    __threadfence();
    if (t == 0) {
        unsigned prev = atomicAdd(&d_ctr, 1u);
        isLast = (prev == gridDim.x - 1) ? 1 : 0;
    }
    __syncthreads();
    if (isLast && t == 0) {
        int s = 0;
        for (int r = 0; r < NREG; r++) {
            d_cursor[r] = s;
            s += (atomicAdd(&d_hist[r], 0) + (GE - 1)) & ~(GE - 1);
        }
        d_ctr = 0;
    }
}

// ---------------- 1) scatter (+ zero d_sums for this run) ----------------
__global__ void k_scatter_and_zero() {
    int e = blockIdx.x * blockDim.x + threadIdx.x;
    if (e < 2 * H) d_sums[e] = 0.0f;
    if (e < N_EDGES) {
        int r = d_regid[e];
        int pos = atomicAdd(&d_cursor[r], 1);
        d_sorted[pos] = e + 1;
    }
}

// ---------------- 2) Q0/Q1: 4 checkpoint chunks x rank-1 updates -----------
__global__ void __launch_bounds__(128) k_q(const float* w1, const float* b1,
                                           const float* b2, const float* w2) {
    __shared__ float w2sh[128][H + 1];
    __shared__ float tbs[H];
    __shared__ int   rankOf[H], idxOf[H];
    __shared__ float mb[H], mw[H], dB[H], dW[H];
    __shared__ int   cix[H];

    int t = threadIdx.x;
    int mg = blockIdx.x & 31, chunk = blockIdx.x >> 5;
    int r0 = chunk * 17;
    int rend = (r0 + 17 < NREG) ? r0 + 17 : NREG;
    int mbase = mg * 128;

    for (int i2 = t; i2 < 128 * H; i2 += 128) {
        int ml = i2 >> 6, k = i2 & 63;
        w2sh[ml][k] = w2[(mbase + ml) * H + k];
    }
    if (t < H) tbs[t] = bp_of(w1, b1, t);
    __syncthreads();
    if (t < H) {
        float my = tbs[t];
        int rank = 0;
        for (int j = 0; j < H; j++) {
            float tj = tbs[j];
            rank += (tj < my) || (tj == my && j < t);
        }
        rankOf[t] = rank;
        idxOf[rank] = t;
    }
    __syncthreads();
    if (t < H) {
        int k = t;
        float w = w1[k], b = b1[k];
        int rk = rankOf[k];
        bool act = (w > 0.0f) ? (rk < r0) : ((w < 0.0f) ? (rk >= r0) : (b > 0.0f));
        mb[k] = act ? b : 0.0f;
        mw[k] = act ? w : 0.0f;
        int kr = idxOf[t];
        float wr = w1[kr], br = b1[kr];
        float sgn = (wr > 0.0f) ? 1.0f : -1.0f;
        dB[t] = sgn * br;
        dW[t] = sgn * wr;
        cix[t] = kr;
    }
    __syncthreads();

    int m = mbase + t;
    int i = m >> 6, o = m & 63;
    int p = (i >> 1) * 128 + 2 * o + (i & 1);   // pair-permuted index
    const float* row = w2sh[t];
    float q0 = b2[m];
    float q1 = 0.0f;
    #pragma unroll 8
    for (int k = 0; k < H; k++) {
        float v = row[k];
        q0 = fmaf(mb[k], v, q0);
        q1 = fmaf(mw[k], v, q1);
    }
    for (int r = r0; r < rend; r++) {
        d_Qbuf[r * (2 * HH) + p]      = q0;
        d_Qbuf[r * (2 * HH) + HH + p] = q1;
        if (r < H) {
            float v = row[cix[r]];
            q0 = fmaf(dB[r], v, q0);
            q1 = fmaf(dW[r], v, q1);
        }
    }
}

// ---------------- 3) message + scatter-add (hot; warp-autonomous) ----------
// Each warp: GE=8 edges, lane covers o=lane and o=lane+32. No block barriers.
__global__ void __launch_bounds__(128, 6) k_msg(const float* x, const float* ea,
                                                const int* ei) {
    __shared__ float2 xs[WARPS][GE][32];    // {x[2c], x[2c+1]} per edge
    __shared__ float  sa[WARPS][GE];
    __shared__ int    ssrc[WARPS][GE];
    __shared__ int    sdst[WARPS][GE];
    __shared__ int    sreg[WARPS][GE];

    int w = threadIdx.x >> 5;
    int lane = threadIdx.x & 31;
    int sbase = blockIdx.x * BLK_SLOTS + w * GE;

    if (lane < GE) {
        int slot = sbase + lane;
        int eid1 = (slot < EPAD) ? d_sorted[slot] : 0;
        int src = -1, dst = 0, r = -1;
        float a = 0.0f;
        if (eid1 > 0) {
            int eid = eid1 - 1;
            a = ea[eid];
            src = ei[eid];
            dst = ei[N_EDGES + eid];
            r = d_regid[eid];
            if (src < 0 || src >= N_NODES || dst < 0 || dst >= N_NODES) {
                src = -1; dst = 0;
            }
        }
        sa[w][lane] = a; ssrc[w][lane] = src;
        sdst[w][lane] = dst; sreg[w][lane] = r;
    }
    __syncwarp();
    int rr = -1;
    #pragma unroll
    for (int j = 0; j < GE; j++) { int rg = sreg[w][j]; rr = (rg > rr) ? rg : rr; }
    if (rr < 0) return;

    // stage x rows as float2
    #pragma unroll
    for (int j = 0; j < GE; j++) {
        int s = ssrc[w][j];
        float2 v = make_float2(0.0f, 0.0f);
        if (s >= 0) v = *reinterpret_cast<const float2*>(x + s * H + 2 * lane);
        xs[w][j][lane] = v;
    }
    __syncwarp();

    const float* Qp = d_Qbuf + rr * (2 * HH);
    float a0a[GE], a1a[GE], a0b[GE], a1b[GE];
    #pragma unroll
    for (int j = 0; j < GE; j++) { a0a[j] = 0.f; a1a[j] = 0.f; a0b[j] = 0.f; a1b[j] = 0.f; }

    #pragma unroll 4
    for (int c = 0; c < 32; c++) {
        const float* base = Qp + c * 128 + 2 * lane;
        float2 q0a = *reinterpret_cast<const float2*>(base);
        float2 q0b = *reinterpret_cast<const float2*>(base + 64);
        float2 q1a = *reinterpret_cast<const float2*>(base + HH);
        float2 q1b = *reinterpret_cast<const float2*>(base + HH + 64);
        #pragma unroll
        for (int j = 0; j < GE; j++) {
            float2 xv = xs[w][j][c];
            a0a[j] = fmaf(xv.x, q0a.x, a0a[j]); a0a[j] = fmaf(xv.y, q0a.y, a0a[j]);
            a0b[j] = fmaf(xv.x, q0b.x, a0b[j]); a0b[j] = fmaf(xv.y, q0b.y, a0b[j]);
            a1a[j] = fmaf(xv.x, q1a.x, a1a[j]); a1a[j] = fmaf(xv.y, q1a.y, a1a[j]);
            a1b[j] = fmaf(xv.x, q1b.x, a1b[j]); a1b[j] = fmaf(xv.y, q1b.y, a1b[j]);
        }
    }
    #pragma unroll
    for (int j = 0; j < GE; j++) {
        bool live = (ssrc[w][j] >= 0);
        float aa = sa[w][j];
        float va = live ? fmaf(aa, a1a[j], a0a[j]) : 0.0f;
        float vb = live ? fmaf(aa, a1b[j], a0b[j]) : 0.0f;
        float vah = __shfl_down_sync(0xFFFFFFFF, va, 1);
        float vbh = __shfl_down_sync(0xFFFFFFFF, vb, 1);
        if (live && (lane & 1) == 0) {
            float* p = d_agg + sdst[w][j] * H + lane;
            asm volatile("red.global.add.v2.f32 [%0], {%1, %2};"
                         :: "l"(p), "f"(va), "f"(vah) : "memory");
            asm volatile("red.global.add.v2.f32 [%0], {%1, %2};"
                         :: "l"(p + 32), "f"(vb), "f"(vbh) : "memory");
        }
    }
}

// ---------------- 4) root GEMM + bias + agg; BN sums via spread atomics ----
__global__ void __launch_bounds__(256) k_root(const float* x, const float* rw,
                                              const float* cb, float* out) {
    __shared__ float rws[HH];
    __shared__ float xrs[4][H];
    __shared__ float red[256];
    int t = threadIdx.x;
    for (int idx = t; idx < HH; idx += 256) {
        int oo = idx >> 6, ii = idx & 63;
        rws[ii * H + oo] = rw[idx];
    }
    int o = t & 63, nl = t >> 6;
    __syncthreads();
    float cbo = cb[o];
    float psum = 0.0f, psq = 0.0f;
    int n0 = blockIdx.x * NPB;
    for (int c = 0; c < NPB; c += 4) {
        int n = n0 + c + nl;
        xrs[nl][o] = x[n * H + o];
        __syncthreads();
        float acc = 0.0f;
        #pragma unroll 8
        for (int i = 0; i < H; i++) acc = fmaf(xrs[nl][i], rws[i * H + o], acc);
        float val = acc + d_agg[n * H + o] + cbo;
        out[n * H + o] = val;
        psum += val;
        psq = fmaf(val, val, psq);
        __syncthreads();
    }
    red[t] = psum; __syncthreads();
    if (nl < 2) red[t] += red[t + 128];
    __syncthreads();
    if (nl == 0) atomicAdd(&d_sums[o], red[t] + red[t + 64]);
    __syncthreads();
    red[t] = psq; __syncthreads();
    if (nl < 2) red[t] += red[t + 128];
    __syncthreads();
    if (nl == 0) atomicAdd(&d_sums[H + o], red[t] + red[t + 64]);
}

// ---------------- 5) BN + relu + residual, then reset scratch for replay ---
__global__ void k_fin(const float* x, const float* gamma,
                      const float* beta, float* out) {
    int idx = blockIdx.x * blockDim.x + threadIdx.x;
    if (idx < N_NODES * H) {
        int o = idx & 63;
        const float invN = 1.0f / (float)N_NODES;
        float mean = d_sums[o] * invN;
        float var  = d_sums[H + o] * invN - mean * mean;
        float istd = rsqrtf(var + 1e-5f);
        float v = out[idx];
        float bn = fmaf((v - mean) * istd, gamma[o], beta[o]);
        out[idx] = x[idx] + fmaxf(bn, 0.0f);
        d_agg[idx] = 0.0f;
        if (idx < EPAD) d_sorted[idx] = 0;
        if (idx < NREG) { d_hist[idx] = 0; d_cursor[idx] = 0; }
    }
}

extern "C" void kernel_launch(void* const* d_in, const int* in_sizes, int n_in,
                              void* d_out, int out_size) {
    const float* x     = (const float*)d_in[0];
    const float* ea    = (const float*)d_in[1];
    const int*   ei    = (const int*)d_in[2];
    const float* w1    = (const float*)d_in[3];
    const float* b1    = (const float*)d_in[4];
    const float* w2    = (const float*)d_in[5];
    const float* b2    = (const float*)d_in[6];
    const float* rw    = (const float*)d_in[7];
    const float* cb    = (const float*)d_in[8];
    const float* gamma = (const float*)d_in[9];
    const float* beta  = (const float*)d_in[10];
    float* out = (float*)d_out;

    k_region<<<(N_EDGES + 255) / 256, 256>>>(ea, w1, b1);
    k_scatter_and_zero<<<(N_EDGES + 255) / 256, 256>>>();
    k_q<<<128, 128>>>(w1, b1, b2, w2);
    k_msg<<<(EPAD + BLK_SLOTS - 1) / BLK_SLOTS, 128>>>(x, ea, ei);  // profiled slot
    k_root<<<RBLOCKS, 256>>>(x, rw, cb, out);
    k_fin<<<(N_NODES * H + 255) / 256, 256>>>(x, gamma, beta, out);
}